// round 5
// baseline (speedup 1.0000x reference)
#include <cuda_runtime.h>
#include <cuda_fp16.h>

#define T_LEN   8192
#define U_DIM   64
#define I_DIM   6
#define M_OUT   16
#define UNFOLDS 6

__device__ __forceinline__ float fast_tanh(float x) {
    float y;
    asm("tanh.approx.f32 %0, %1;" : "=f"(y) : "f"(x));
    return y;
}

__device__ __forceinline__ unsigned long long pack_f32x2(float lo, float hi) {
    unsigned long long r;
    asm("mov.b64 %0, {%1, %2};" : "=l"(r) : "f"(lo), "f"(hi));
    return r;
}

// One block (128 threads) per batch element. tid = j*2 + c.
//   j in [0,64): post-synaptic neuron owned by 2 lanes
//   c in [0,2):  split of the 64 pre-synaptic neurons (32 each)
// Hybrid precision: per thread, the 16 largest-w synapses use tanh.approx.f32,
// the 16 smallest-w pair into 8 tanh.approx.f16x2 (fp32 args/accum everywhere).
__global__ void __launch_bounds__(128, 2)
ltc_seq_kernel(const float* __restrict__ x,
               const float* __restrict__ gleak, const float* __restrict__ vleak,
               const float* __restrict__ cm,
               const float* __restrict__ sigma, const float* __restrict__ mu,
               const float* __restrict__ w,     const float* __restrict__ erev,
               const float* __restrict__ ssig,  const float* __restrict__ smu,
               const float* __restrict__ sw,    const float* __restrict__ serev,
               const float* __restrict__ iw,    const float* __restrict__ ib,
               const float* __restrict__ ow,    const float* __restrict__ ob,
               float* __restrict__ out)
{
    const int b   = blockIdx.x;
    const int tid = threadIdx.x;
    const int j   = tid >> 1;
    const int c   = tid & 1;

    // hidden state fp32, double-buffered (buffer stride = 256 bytes)
    __shared__ __align__(16) float vbuf[2][U_DIM];
    // init-time scratch (per-thread private columns; padded to kill bank conflicts)
    __shared__ float          scratch[128][33];
    __shared__ unsigned char  order  [128][33];

    // ---- rank this thread's 32 synapses by w (descending) ----
    for (int k = 0; k < 32; ++k)
        scratch[tid][k] = w[(c * 32 + k) * U_DIM + j];
    for (int r = 0; r < 32; ++r) {
        float best = -1.f; int bi = 0;
        for (int k = 0; k < 32; ++k) {
            const float v = scratch[tid][k];
            if (v > best) { best = v; bi = k; }
        }
        order[tid][r] = (unsigned char)bi;
        scratch[tid][bi] = -2.f;
    }

    // ---- constants ----
    // sigmoid(z) = 0.5 + 0.5*tanh(z/2)
    // den contribution: 0.5*w + 0.5*w*tanh(0.5*(v_i-mu)*sigma); num: same * erev
    float pWH = 0.f, pWE = 0.f;
    for (int k = 0; k < 32; ++k) {
        const int idx = (c * 32 + k) * U_DIM + j;
        const float wh = 0.5f * w[idx];
        pWH += wh;
        pWE += wh * erev[idx];
    }
    pWH += __shfl_xor_sync(0xffffffffu, pWH, 1);
    pWE += __shfl_xor_sync(0xffffffffu, pWE, 1);

    // f32 path: 16 largest-w (ranks 0..15)
    float A[16], B[16], WE[16], WH[16];
    int   voff[32];                       // byte offsets into vbuf[0]
#pragma unroll
    for (int r = 0; r < 16; ++r) {
        const int k   = order[tid][r];
        const int gi  = c * 32 + k;
        const int idx = gi * U_DIM + j;
        const float a = 0.5f * sigma[idx];
        A [r] = a;
        B [r] = -mu[idx] * a;
        const float wh = 0.5f * w[idx];
        WH[r] = wh;
        WE[r] = wh * erev[idx];
        voff[r] = gi * 4;
    }
    // f16x2 path: 16 smallest-w (ranks 16..31) as 8 pairs
    unsigned long long A2[8], B2[8], WE2[8], WH2[8];
#pragma unroll
    for (int p = 0; p < 8; ++p) {
        const int k0   = order[tid][16 + 2 * p];
        const int k1   = order[tid][17 + 2 * p];
        const int gi0  = c * 32 + k0;
        const int gi1  = c * 32 + k1;
        const int idx0 = gi0 * U_DIM + j;
        const int idx1 = gi1 * U_DIM + j;
        const float a0 = 0.5f * sigma[idx0];
        const float a1 = 0.5f * sigma[idx1];
        A2[p] = pack_f32x2(a0, a1);
        B2[p] = pack_f32x2(-mu[idx0] * a0, -mu[idx1] * a1);
        const float wh0 = 0.5f * w[idx0];
        const float wh1 = 0.5f * w[idx1];
        WH2[p] = pack_f32x2(wh0, wh1);
        WE2[p] = pack_f32x2(wh0 * erev[idx0], wh1 * erev[idx1]);
        voff[16 + 2 * p] = gi0 * 4;
        voff[17 + 2 * p] = gi1 * 4;
    }

    // ---- sensory constants (fp32, fp32 tanh; 3 inputs per lane) ----
    float sSWH = 0.f, sSWE = 0.f;
#pragma unroll
    for (int i = 0; i < I_DIM; ++i) {
        const float swh = 0.5f * sw[i * U_DIM + j];
        sSWH += swh;
        sSWE += swh * serev[i * U_DIM + j];
    }
    float SA[3], SB[3], SWc[3], SE[3];
#pragma unroll
    for (int m = 0; m < 3; ++m) {
        const int si = c * 3 + m;
        const float sg = ssig[si * U_DIM + j];
        SA [m] = 0.5f * iw[si] * sg;
        SB [m] = 0.5f * (ib[si] - smu[si * U_DIM + j]) * sg;
        SWc[m] = 0.5f * sw[si * U_DIM + j];
        SE [m] = SWc[m] * serev[si * U_DIM + j];
    }

    // ---- per-j scalar constants ----
    const float gl  = gleak[j];
    const float vl  = vleak[j];
    const float cmt = cm[j] * (float)UNFOLDS;
    const float hNC = 0.5f * (gl * vl + pWE + sSWE);   // halved: counted by both lanes
    const float hDC = 0.5f * (cmt + gl + pWH + sSWH + 1e-8f);
    const float owj = ow[j & (M_OUT - 1)];
    const float obj = ob[j & (M_OUT - 1)];

    // ---- init hidden state ----
    if (tid < U_DIM) { vbuf[0][tid] = 0.f; vbuf[1][tid] = 0.f; }
    __syncthreads();

    float vj = 0.f;
    const float* xrow = x + (size_t)b * T_LEN * I_DIM + c * 3;
    float*       orow = out + (size_t)b * T_LEN * M_OUT;

    float xr0 = __ldg(xrow + 0);
    float xr1 = __ldg(xrow + 1);
    float xr2 = __ldg(xrow + 2);

    const char* vbase = (const char*)&vbuf[0][0];

    for (int t = 0; t < T_LEN; ++t) {
        // sensory partials (constant across unfolds), lane-partial
        const float s0 = fast_tanh(fmaf(xr0, SA[0], SB[0]));
        const float s1 = fast_tanh(fmaf(xr1, SA[1], SB[1]));
        const float s2 = fast_tanh(fmaf(xr2, SA[2], SB[2]));
        const float ns = fmaf(SE[0], s0, fmaf(SE[1], s1, fmaf(SE[2], s2, hNC)));
        const float ds = fmaf(SWc[0], s0, fmaf(SWc[1], s1, fmaf(SWc[2], s2, hDC)));

        // prefetch x for next step
        {
            const int tn = (t + 1 < T_LEN) ? (t + 1) : t;
            const float* xn = xrow + (size_t)tn * I_DIM;
            xr0 = __ldg(xn + 0);
            xr1 = __ldg(xn + 1);
            xr2 = __ldg(xn + 2);
        }

#pragma unroll
        for (int u = 0; u < UNFOLDS; ++u) {
            const char* vb = vbase + (u & 1) * (U_DIM * 4);   // compile-time immediate

            float nr = ns, dr = ds;
            // f32 path: 16 largest-w synapses
#pragma unroll
            for (int r = 0; r < 16; ++r) {
                const float vi = *(const float*)(vb + voff[r]);
                const float s  = fast_tanh(fmaf(vi, A[r], B[r]));
                nr = fmaf(WE[r], s, nr);
                dr = fmaf(WH[r], s, dr);
            }
            // f16x2 path: 16 smallest-w synapses (8 pairs), fp32 args + accum
            unsigned long long nr2 = pack_f32x2(0.f, 0.f);
            unsigned long long dr2 = nr2;
#pragma unroll
            for (int p = 0; p < 8; ++p) {
                const float v0 = *(const float*)(vb + voff[16 + 2 * p]);
                const float v1 = *(const float*)(vb + voff[17 + 2 * p]);
                const unsigned long long V2 = pack_f32x2(v0, v1);
                asm("{\n\t"
                    ".reg .b64 arg2, sf2;\n\t"
                    ".reg .f32 alo, ahi, flo, fhi;\n\t"
                    ".reg .b32 h2, st2;\n\t"
                    ".reg .f16 hlo, hhi;\n\t"
                    "fma.rn.f32x2 arg2, %2, %3, %4;\n\t"      // arg = v*A + B (fp32)
                    "mov.b64 {alo, ahi}, arg2;\n\t"
                    "cvt.rn.f16x2.f32 h2, ahi, alo;\n\t"
                    "tanh.approx.f16x2 st2, h2;\n\t"          // 2 tanh / 1 MUFU
                    "mov.b32 {hlo, hhi}, st2;\n\t"
                    "cvt.f32.f16 flo, hlo;\n\t"
                    "cvt.f32.f16 fhi, hhi;\n\t"
                    "mov.b64 sf2, {flo, fhi};\n\t"
                    "fma.rn.f32x2 %0, %5, sf2, %0;\n\t"
                    "fma.rn.f32x2 %1, %6, sf2, %1;\n\t"
                    "}"
                    : "+l"(nr2), "+l"(dr2)
                    : "l"(V2), "l"(A2[p]), "l"(B2[p]), "l"(WE2[p]), "l"(WH2[p]));
            }
            float nlo, nhi, dlo, dhi;
            asm("mov.b64 {%0, %1}, %2;" : "=f"(nlo), "=f"(nhi) : "l"(nr2));
            asm("mov.b64 {%0, %1}, %2;" : "=f"(dlo), "=f"(dhi) : "l"(dr2));
            nr += nlo + nhi;
            dr += dlo + dhi;
            nr += __shfl_xor_sync(0xffffffffu, nr, 1);
            dr += __shfl_xor_sync(0xffffffffu, dr, 1);
            vj = __fdividef(fmaf(cmt, vj, nr), dr);
            if (c == 0) vbuf[(u & 1) ^ 1][j] = vj;
            __syncthreads();
        }

        if (c == 0 && j < M_OUT)
            orow[t * M_OUT + j] = fmaf(vj, owj, obj);
    }
}

extern "C" void kernel_launch(void* const* d_in, const int* in_sizes, int n_in,
                              void* d_out, int out_size)
{
    const float* x      = (const float*)d_in[0];
    const float* gleak  = (const float*)d_in[1];
    const float* vleak  = (const float*)d_in[2];
    const float* cm     = (const float*)d_in[3];
    const float* sigma  = (const float*)d_in[4];
    const float* mu     = (const float*)d_in[5];
    const float* w      = (const float*)d_in[6];
    const float* erev   = (const float*)d_in[7];
    const float* ssig   = (const float*)d_in[8];
    const float* smu    = (const float*)d_in[9];
    const float* sw     = (const float*)d_in[10];
    const float* serev  = (const float*)d_in[11];
    const float* iw     = (const float*)d_in[12];
    const float* ib     = (const float*)d_in[13];
    const float* ow     = (const float*)d_in[14];
    const float* ob     = (const float*)d_in[15];
    float* out = (float*)d_out;

    const int batch = in_sizes[0] / (T_LEN * I_DIM);  // 256
    ltc_seq_kernel<<<batch, 128>>>(x, gleak, vleak, cm, sigma, mu, w, erev,
                                   ssig, smu, sw, serev, iw, ib, ow, ob, out);
}